// round 11
// baseline (speedup 1.0000x reference)
#include <cuda_runtime.h>
#include <cuda_bf16.h>
#include <cstdint>

#define PP 32      // num networks
#define HH 128     // hidden
#define BB 32      // batch
#define TT 256     // seq len
#define CHUNK 4    // CTAs per network (cluster size)
#define NTHREADS 256
#define KTILES 10  // K = 160 = 10 x 16

// B buffer: per n (batch), PADW words (u32 = packed bf16 k-pair), conflict-free
#define PADW 88
#define BBYTES (32 * PADW * 4)          // 11264 per buffer

// smem byte offsets
#define OFF_BIAS 0                       // 4*32 f32
#define OFF_WOUT 512                     // 32 f32
#define OFF_B0   1024                    // 4 buffers: buf0_hi, buf0_lo, buf1_hi, buf1_lo
#define SMEM_BYTES (1024 + 4 * BBYTES)   // 46080

// packed X scratch: [b][t][16 words] for k<32 region, hi and lo
__device__ uint32_t Xp_hi_g[BB * TT * 16];
__device__ uint32_t Xp_lo_g[BB * TT * 16];

__device__ __forceinline__ float tanha(float x) {
    float y; asm("tanh.approx.f32 %0, %1;" : "=f"(y) : "f"(x)); return y;
}
__device__ __forceinline__ float sigf(float x) {
    return fmaf(0.5f, tanha(0.5f * x), 0.5f);
}

__device__ __forceinline__ uint32_t pack_bf2(float lo_k, float hi_k) {
    unsigned short a = __bfloat16_as_ushort(__float2bfloat16(lo_k));
    unsigned short b = __bfloat16_as_ushort(__float2bfloat16(hi_k));
    return (uint32_t)a | ((uint32_t)b << 16);
}

__device__ __forceinline__ void mma16816(float* d, const uint32_t* a, uint32_t b0, uint32_t b1) {
    asm volatile(
        "mma.sync.aligned.m16n8k16.row.col.f32.bf16.bf16.f32 "
        "{%0,%1,%2,%3}, {%4,%5,%6,%7}, {%8,%9}, {%0,%1,%2,%3};"
        : "+f"(d[0]), "+f"(d[1]), "+f"(d[2]), "+f"(d[3])
        : "r"(a[0]), "r"(a[1]), "r"(a[2]), "r"(a[3]), "r"(b0), "r"(b1));
}

#define CLUSTER_ARRIVE() asm volatile("barrier.cluster.arrive.aligned;" ::: "memory")
#define CLUSTER_WAIT()   asm volatile("barrier.cluster.wait.aligned;"   ::: "memory")

__global__ void init_out_kernel(float* __restrict__ out, const float* __restrict__ b_out) {
    int i = blockIdx.x * blockDim.x + threadIdx.x;
    if (i < BB * TT * PP) out[i] = b_out[i & (PP - 1)];
}

// split X into packed hi/lo bf16 word layout: word w of n holds k-pair at
// d0 = (w>>3)*16 + ((w&7)>>1)*2 + (w&1)*8
__global__ void xsplit_kernel(const float* __restrict__ X) {
    int i = blockIdx.x * blockDim.x + threadIdx.x;
    if (i >= BB * TT * 16) return;
    int w = i & 15;
    int bt = i >> 4;              // b*TT + t
    int d0 = ((w >> 3) * 16) + (((w & 7) >> 1) * 2) + ((w & 1) * 8);
    float v0 = X[(size_t)bt * PP + d0];
    float v1 = X[(size_t)bt * PP + d0 + 1];
    __nv_bfloat16 h0 = __float2bfloat16(v0);
    __nv_bfloat16 h1 = __float2bfloat16(v1);
    float l0 = v0 - __bfloat162float(h0);
    float l1 = v1 - __bfloat162float(h1);
    Xp_hi_g[i] = (uint32_t)__bfloat16_as_ushort(h0) | ((uint32_t)__bfloat16_as_ushort(h1) << 16);
    Xp_lo_g[i] = pack_bf2(l0, l1);
}

extern __shared__ char smem_c[];

__global__ void __cluster_dims__(CHUNK, 1, 1) __launch_bounds__(NTHREADS, 1)
clstm_mma_kernel(const float* __restrict__ Wih,
                 const float* __restrict__ Whh,
                 const float* __restrict__ bih,
                 const float* __restrict__ bhh,
                 const float* __restrict__ Wout,
                 float* __restrict__ out)
{
    const int tid  = threadIdx.x;
    const int lane = tid & 31;
    const int wid  = tid >> 5;           // 8 warps
    const int r    = lane >> 2;          // fragment row group (0..7)
    const int tg   = lane & 3;           // fragment thread-in-group

    uint32_t rank;
    asm("mov.u32 %0, %%cluster_ctarank;" : "=r"(rank));
    const int n  = blockIdx.x >> 2;      // network id
    const int j0 = (int)rank * 32;

    // warp tiling: jg = j-group of 8 (0..3), nh = batch half (0..1)
    const int jg = wid >> 1;
    const int nh = wid & 1;
    const int j  = jg * 8 + r;           // this thread's j (within CTA slice)
    const int bbase = nh * 16;

    // ---- zero all B buffers (h region must start at 0) ----
    {
        uint4 z = make_uint4(0, 0, 0, 0);
        for (int i = tid; i < 4 * BBYTES / 16; i += NTHREADS)
            reinterpret_cast<uint4*>(smem_c + OFF_B0)[i] = z;
    }

    // ---- bias + wout ----
    for (int idx = tid; idx < 4 * 32; idx += NTHREADS) {
        int g = idx >> 5, jl = idx & 31;
        int row = n * 4 * HH + g * HH + j0 + jl;
        *reinterpret_cast<float*>(smem_c + OFF_BIAS + idx * 4) = bih[row] + bhh[row];
    }
    if (tid < 32) *reinterpret_cast<float*>(smem_c + OFF_WOUT + tid * 4) = Wout[n * HH + j0 + tid];

    // zero-loop / bias / wout writes must complete before X staging or bias reads
    __syncthreads();

    // ---- load A fragments: 2 m-tiles (gates {0,1} and {2,3}) for this warp's j's ----
    // m-tile mt rows: 0..7 -> gate mt*2, j = jg*8 + row; 8..15 -> gate mt*2+1, same j.
    uint32_t Ahi[2][KTILES][4], Alo[2][KTILES][4];
#pragma unroll
    for (int mt = 0; mt < 2; ++mt) {
        const size_t growA = (size_t)(n * 4 * HH + (mt * 2 + 0) * HH + j0 + j);
        const size_t growB = (size_t)(n * 4 * HH + (mt * 2 + 1) * HH + j0 + j);
#pragma unroll
        for (int kt = 0; kt < KTILES; ++kt) {
#pragma unroll
            for (int e = 0; e < 4; ++e) {
                // e: 0 -> (gateA, k0), 1 -> (gateB, k0), 2 -> (gateA, k0+8), 3 -> (gateB, k0+8)
                size_t grow = (e & 1) ? growB : growA;
                int k = kt * 16 + tg * 2 + ((e >> 1) * 8);
                float v0, v1;
                if (k < PP) {
                    v0 = Wih[grow * PP + k];
                    v1 = Wih[grow * PP + k + 1];
                } else {
                    v0 = Whh[grow * HH + (k - PP)];
                    v1 = Whh[grow * HH + (k - PP) + 1];
                }
                __nv_bfloat16 h0 = __float2bfloat16(v0);
                __nv_bfloat16 h1 = __float2bfloat16(v1);
                Ahi[mt][kt][e] = (uint32_t)__bfloat16_as_ushort(h0) | ((uint32_t)__bfloat16_as_ushort(h1) << 16);
                Alo[mt][kt][e] = pack_bf2(v0 - __bfloat162float(h0), v1 - __bfloat162float(h1));
            }
        }
    }

    // ---- stage X(t=0) into buffer 0 (after the sync: region is stably zeroed) ----
    const int xb  = tid >> 3;
    const int xwp = (tid & 7) * 2;
    {
        uint2 vh = *reinterpret_cast<const uint2*>(&Xp_hi_g[((size_t)xb * TT + 0) * 16 + xwp]);
        uint2 vl = *reinterpret_cast<const uint2*>(&Xp_lo_g[((size_t)xb * TT + 0) * 16 + xwp]);
        *reinterpret_cast<uint2*>(smem_c + OFF_B0 + (xb * PADW + xwp) * 4) = vh;
        *reinterpret_cast<uint2*>(smem_c + OFF_B0 + BBYTES + (xb * PADW + xwp) * 4) = vl;
    }

    // per-thread constants for this thread's j
    const float biasI = *reinterpret_cast<float*>(smem_c + OFF_BIAS + (0 * 32 + j) * 4);
    const float biasF = *reinterpret_cast<float*>(smem_c + OFF_BIAS + (1 * 32 + j) * 4);
    const float biasG = *reinterpret_cast<float*>(smem_c + OFF_BIAS + (2 * 32 + j) * 4);
    const float biasO = *reinterpret_cast<float*>(smem_c + OFF_BIAS + (3 * 32 + j) * 4);
    const float wout  = *reinterpret_cast<float*>(smem_c + OFF_WOUT + j * 4);

    // this j-pair's h-write WORD offset (even k of the pair): khe = 32 + j0 + (j & ~1)
    const int khe = PP + j0 + (j & ~1);
    const uint32_t hwrd4 = (uint32_t)((khe >> 4) * 8 + ((khe >> 1) & 3) * 2 + ((khe >> 3) & 1)) * 4;

    // smem base + peer bases
    uint32_t sbase;
    asm("{ .reg .u64 t0; cvta.to.shared.u64 t0, %1; cvt.u32.u64 %0, t0; }" : "=r"(sbase) : "l"(smem_c));
    uint32_t peer_base[CHUNK];
#pragma unroll
    for (int rr = 0; rr < CHUNK; ++rr)
        asm("mapa.shared::cluster.u32 %0, %1, %2;" : "=r"(peer_base[rr]) : "r"(sbase), "r"(rr));

    // cell state: index (nt*2 + c) -> b = bbase + nt*8 + tg*2 + c
    float c[4] = {0.0f, 0.0f, 0.0f, 0.0f};
    int buf = 0;

    // init done: release local init stores to the cluster (arrive #1)
    CLUSTER_ARRIVE();

    for (int t = 0; t < TT; ++t) {
        // prefetch X(t+1) from global BEFORE the wait — latency hidden by barrier+MMA
        int tn = (t + 1 < TT) ? (t + 1) : t;
        uint2 pvh = *reinterpret_cast<const uint2*>(&Xp_hi_g[((size_t)xb * TT + tn) * 16 + xwp]);
        uint2 pvl = *reinterpret_cast<const uint2*>(&Xp_lo_g[((size_t)xb * TT + tn) * 16 + xwp]);

        // wait: all CTAs published h(t) + X(t) stores (arrive #(t+1))
        CLUSTER_WAIT();

        const char* bufhi = smem_c + OFF_B0 + buf * 2 * BBYTES;
        const char* buflo = bufhi + BBYTES;

        // ---- split-GEMM: acc = A_hi*B_hi + A_hi*B_lo + A_lo*B_hi ----
        // acc[mt][nt][4]: d0,d1 = gate mt*2   (j, b = bbase+nt*8+tg*2 {,+1})
        //                 d2,d3 = gate mt*2+1 (same j, same b's)
        float acc[2][2][4];
#pragma unroll
        for (int mt = 0; mt < 2; ++mt)
#pragma unroll
            for (int nt = 0; nt < 2; ++nt)
#pragma unroll
                for (int e = 0; e < 4; ++e) acc[mt][nt][e] = 0.0f;

#pragma unroll
        for (int kt = 0; kt < KTILES; ++kt) {
            uint2 bh[2], bl[2];
#pragma unroll
            for (int nt = 0; nt < 2; ++nt) {
                uint32_t off = ((uint32_t)(bbase + nt * 8 + r) * PADW + kt * 8 + tg * 2) * 4;
                bh[nt] = *reinterpret_cast<const uint2*>(bufhi + off);
                bl[nt] = *reinterpret_cast<const uint2*>(buflo + off);
            }
#pragma unroll
            for (int mt = 0; mt < 2; ++mt) {
#pragma unroll
                for (int nt = 0; nt < 2; ++nt) {
                    mma16816(acc[mt][nt], Ahi[mt][kt], bh[nt].x, bh[nt].y);
                    mma16816(acc[mt][nt], Ahi[mt][kt], bl[nt].x, bl[nt].y);
                    mma16816(acc[mt][nt], Alo[mt][kt], bh[nt].x, bh[nt].y);
                }
            }
        }

        const uint32_t offB_next = (uint32_t)(OFF_B0 + (buf ^ 1) * 2 * BBYTES);

        // ---- epilogue straight from accumulators: no smem staging, no syncthreads ----
        float pout[4];
#pragma unroll
        for (int nt = 0; nt < 2; ++nt) {
#pragma unroll
            for (int cc2 = 0; cc2 < 2; ++cc2) {
                int idx = nt * 2 + cc2;
                int b = bbase + nt * 8 + tg * 2 + cc2;
                float gi = acc[0][nt][cc2]     + biasI;
                float gf = acc[0][nt][2 + cc2] + biasF;
                float gg = acc[1][nt][cc2]     + biasG;
                float go = acc[1][nt][2 + cc2] + biasO;
                float ii = sigf(gi);
                float ff = sigf(gf);
                float g2 = tanha(gg);
                float oo = sigf(go);
                float ncell = fmaf(ff, c[idx], ii * g2);
                c[idx] = ncell;
                float h = oo * tanha(ncell);

                __nv_bfloat16 hhb = __float2bfloat16(h);
                float rem = h - __bfloat162float(hhb);
                uint32_t vh = (uint32_t)__bfloat16_as_ushort(hhb);
                uint32_t vl = (uint32_t)__bfloat16_as_ushort(__float2bfloat16(rem));

                // pair j (even) with j+1 (odd): lanes r, r^1 differ by lane bit 2
                uint32_t vhp = __shfl_xor_sync(0xffffffffu, vh, 4);
                uint32_t vlp = __shfl_xor_sync(0xffffffffu, vl, 4);
                if (!(r & 1)) {
                    uint32_t wordh = vh | (vhp << 16);
                    uint32_t wordl = vl | (vlp << 16);
                    uint32_t oh = offB_next + (uint32_t)b * (PADW * 4) + hwrd4;
                    uint32_t ol = oh + BBYTES;
                    // own CTA via plain shared store
                    *reinterpret_cast<uint32_t*>(smem_c + oh) = wordh;
                    *reinterpret_cast<uint32_t*>(smem_c + ol) = wordl;
                    // peers via full-word cluster stores
#pragma unroll
                    for (int rr = 0; rr < CHUNK; ++rr) {
                        if (rr != (int)rank) {
                            asm volatile("st.shared::cluster.u32 [%0], %1;" :: "r"(peer_base[rr] + oh), "r"(wordh) : "memory");
                            asm volatile("st.shared::cluster.u32 [%0], %1;" :: "r"(peer_base[rr] + ol), "r"(wordl) : "memory");
                        }
                    }
                }
                pout[idx] = h * wout;
            }
        }

        // ---- stage X(t+1) from prefetch regs into next buffer ----
        *reinterpret_cast<uint2*>(smem_c + offB_next + (xb * PADW + xwp) * 4) = pvh;
        *reinterpret_cast<uint2*>(smem_c + offB_next + BBYTES + (xb * PADW + xwp) * 4) = pvl;

        // release this step's stores to the cluster; head work hides under peer skew
        CLUSTER_ARRIVE();

        // head: reduce over the warp's 8 j's (r axis: lane bits 2,3,4), then atomic
#pragma unroll
        for (int i = 0; i < 4; ++i) {
            pout[i] += __shfl_xor_sync(0xffffffffu, pout[i], 4);
            pout[i] += __shfl_xor_sync(0xffffffffu, pout[i], 8);
            pout[i] += __shfl_xor_sync(0xffffffffu, pout[i], 16);
        }
        if (r == 0) {
#pragma unroll
            for (int i = 0; i < 4; ++i) {
                int b = bbase + (i >> 1) * 8 + tg * 2 + (i & 1);
                atomicAdd(&out[((size_t)b * TT + t) * PP + n], pout[i]);
            }
        }

        buf ^= 1;
    }

    // consume the final arrive; no CTA exits while peer stores may be in flight
    CLUSTER_WAIT();
}

extern "C" void kernel_launch(void* const* d_in, const int* in_sizes, int n_in,
                              void* d_out, int out_size) {
    const float* X    = (const float*)d_in[0];
    const float* Wih  = (const float*)d_in[1];
    const float* Whh  = (const float*)d_in[2];
    const float* bih  = (const float*)d_in[3];
    const float* bhh  = (const float*)d_in[4];
    const float* Wout = (const float*)d_in[5];
    const float* bout = (const float*)d_in[6];
    float* out = (float*)d_out;

    cudaFuncSetAttribute(clstm_mma_kernel, cudaFuncAttributeMaxDynamicSharedMemorySize, SMEM_BYTES);

    init_out_kernel<<<(BB * TT * PP + 255) / 256, 256>>>(out, bout);
    xsplit_kernel<<<(BB * TT * 16 + 255) / 256, 256>>>(X);
    clstm_mma_kernel<<<PP * CHUNK, NTHREADS, SMEM_BYTES>>>(Wih, Whh, bih, bhh, Wout, out);
}

// round 12
// speedup vs baseline: 1.0445x; 1.0445x over previous
#include <cuda_runtime.h>
#include <cuda_bf16.h>
#include <cstdint>

#define PP 32      // num networks
#define HH 128     // hidden
#define BB 32      // batch
#define TT 256     // seq len
#define CHUNK 4    // CTAs per network (cluster size)
#define NTHREADS 256
#define KTILES 10  // K = 160 = 10 x 16

// B buffer: per n (batch), PADW words (u32 = packed bf16 k-pair), conflict-free
#define PADW 88
#define BBYTES (32 * PADW * 4)          // 11264 per buffer

// smem byte offsets
#define OFF_BIAS 0                       // 4*32 f32
#define OFF_WOUT 512                     // 32 f32
#define OFF_B0   1024                    // 4 buffers: buf0_hi, buf0_lo, buf1_hi, buf1_lo
#define OFF_S    (1024 + 4 * BBYTES)     // D staging: [4 g][32 jl][34 b] f32
#define S_PAD    34
#define SMEM_BYTES (OFF_S + 4 * 32 * S_PAD * 4)   // 63488

// packed X scratch: [b][t][16 words] for k<32 region, hi and lo
__device__ uint32_t Xp_hi_g[BB * TT * 16];
__device__ uint32_t Xp_lo_g[BB * TT * 16];

__device__ __forceinline__ float tanha(float x) {
    float y; asm("tanh.approx.f32 %0, %1;" : "=f"(y) : "f"(x)); return y;
}
__device__ __forceinline__ float sigf(float x) {
    return fmaf(0.5f, tanha(0.5f * x), 0.5f);
}

__device__ __forceinline__ uint32_t pack_bf2(float lo_k, float hi_k) {
    unsigned short a = __bfloat16_as_ushort(__float2bfloat16(lo_k));
    unsigned short b = __bfloat16_as_ushort(__float2bfloat16(hi_k));
    return (uint32_t)a | ((uint32_t)b << 16);
}

__device__ __forceinline__ void mma16816(float* d, const uint32_t* a, uint32_t b0, uint32_t b1) {
    asm volatile(
        "mma.sync.aligned.m16n8k16.row.col.f32.bf16.bf16.f32 "
        "{%0,%1,%2,%3}, {%4,%5,%6,%7}, {%8,%9}, {%0,%1,%2,%3};"
        : "+f"(d[0]), "+f"(d[1]), "+f"(d[2]), "+f"(d[3])
        : "r"(a[0]), "r"(a[1]), "r"(a[2]), "r"(a[3]), "r"(b0), "r"(b1));
}

#define CLUSTER_ARRIVE() asm volatile("barrier.cluster.arrive.aligned;" ::: "memory")
#define CLUSTER_WAIT()   asm volatile("barrier.cluster.wait.aligned;"   ::: "memory")

__global__ void init_out_kernel(float* __restrict__ out, const float* __restrict__ b_out) {
    int i = blockIdx.x * blockDim.x + threadIdx.x;
    if (i < BB * TT * PP) out[i] = b_out[i & (PP - 1)];
}

// split X into packed hi/lo bf16 word layout: word w of n holds k-pair at
// d0 = (w>>3)*16 + ((w&7)>>1)*2 + (w&1)*8
__global__ void xsplit_kernel(const float* __restrict__ X) {
    int i = blockIdx.x * blockDim.x + threadIdx.x;
    if (i >= BB * TT * 16) return;
    int w = i & 15;
    int bt = i >> 4;              // b*TT + t
    int d0 = ((w >> 3) * 16) + (((w & 7) >> 1) * 2) + ((w & 1) * 8);
    float v0 = X[(size_t)bt * PP + d0];
    float v1 = X[(size_t)bt * PP + d0 + 1];
    __nv_bfloat16 h0 = __float2bfloat16(v0);
    __nv_bfloat16 h1 = __float2bfloat16(v1);
    float l0 = v0 - __bfloat162float(h0);
    float l1 = v1 - __bfloat162float(h1);
    Xp_hi_g[i] = (uint32_t)__bfloat16_as_ushort(h0) | ((uint32_t)__bfloat16_as_ushort(h1) << 16);
    Xp_lo_g[i] = pack_bf2(l0, l1);
}

extern __shared__ char smem_c[];

__global__ void __cluster_dims__(CHUNK, 1, 1) __launch_bounds__(NTHREADS, 1)
clstm_mma_kernel(const float* __restrict__ Wih,
                 const float* __restrict__ Whh,
                 const float* __restrict__ bih,
                 const float* __restrict__ bhh,
                 const float* __restrict__ Wout,
                 float* __restrict__ out)
{
    const int tid  = threadIdx.x;
    const int lane = tid & 31;
    const int wid  = tid >> 5;           // 8 warps
    const int r    = lane >> 2;          // fragment row group
    const int tg   = lane & 3;           // fragment thread-in-group

    uint32_t rank;
    asm("mov.u32 %0, %%cluster_ctarank;" : "=r"(rank));
    const int n  = blockIdx.x >> 2;      // network id
    const int j0 = (int)rank * 32;

    float* S = reinterpret_cast<float*>(smem_c + OFF_S);

    // ---- zero all B buffers (h region must start at 0) ----
    {
        uint4 z = make_uint4(0, 0, 0, 0);
        for (int i = tid; i < 4 * BBYTES / 16; i += NTHREADS)
            reinterpret_cast<uint4*>(smem_c + OFF_B0)[i] = z;
    }

    // ---- bias + wout ----
    for (int idx = tid; idx < 4 * 32; idx += NTHREADS) {
        int g = idx >> 5, jl = idx & 31;
        int row = n * 4 * HH + g * HH + j0 + jl;
        *reinterpret_cast<float*>(smem_c + OFF_BIAS + idx * 4) = bih[row] + bhh[row];
    }
    if (tid < 32) *reinterpret_cast<float*>(smem_c + OFF_WOUT + tid * 4) = Wout[n * HH + j0 + tid];

    // zero-loop / bias / wout writes must complete before X staging or bias reads
    __syncthreads();

    // ---- load A fragments (weights) into registers, hi/lo split ----
    // warp w covers gate-rows m = w*16 + {r, r+8}; gate g = w>>1, jl = m&31
    uint32_t Ahi[KTILES][4], Alo[KTILES][4];
    {
        const int g = wid >> 1;
        const int m0 = wid * 16 + r;
        const int m1 = m0 + 8;
        const int jl0 = m0 & 31, jl1 = m1 & 31;
        const size_t grow0 = (size_t)(n * 4 * HH + g * HH + j0 + jl0);
        const size_t grow1 = (size_t)(n * 4 * HH + g * HH + j0 + jl1);
#pragma unroll
        for (int kt = 0; kt < KTILES; ++kt) {
#pragma unroll
            for (int e = 0; e < 4; ++e) {
                // e: 0 -> (m0, k0), 1 -> (m1, k0), 2 -> (m0, k0+8), 3 -> (m1, k0+8)
                size_t grow = (e & 1) ? grow1 : grow0;
                int k = kt * 16 + tg * 2 + ((e >> 1) * 8);
                float v0, v1;
                if (k < PP) {
                    v0 = Wih[grow * PP + k];
                    v1 = Wih[grow * PP + k + 1];
                } else {
                    v0 = Whh[grow * HH + (k - PP)];
                    v1 = Whh[grow * HH + (k - PP) + 1];
                }
                __nv_bfloat16 h0 = __float2bfloat16(v0);
                __nv_bfloat16 h1 = __float2bfloat16(v1);
                Ahi[kt][e] = (uint32_t)__bfloat16_as_ushort(h0) | ((uint32_t)__bfloat16_as_ushort(h1) << 16);
                Alo[kt][e] = pack_bf2(v0 - __bfloat162float(h0), v1 - __bfloat162float(h1));
            }
        }
    }

    // ---- stage X(t=0) into buffer 0 (after the sync: region is stably zeroed) ----
    const int xb  = tid >> 3;
    const int xwp = (tid & 7) * 2;
    {
        uint2 vh = *reinterpret_cast<const uint2*>(&Xp_hi_g[((size_t)xb * TT + 0) * 16 + xwp]);
        uint2 vl = *reinterpret_cast<const uint2*>(&Xp_lo_g[((size_t)xb * TT + 0) * 16 + xwp]);
        *reinterpret_cast<uint2*>(smem_c + OFF_B0 + (xb * PADW + xwp) * 4) = vh;
        *reinterpret_cast<uint2*>(smem_c + OFF_B0 + BBYTES + (xb * PADW + xwp) * 4) = vl;
    }

    // per-thread epilogue constants (post-barrier: values are valid)
    const float biasI = *reinterpret_cast<float*>(smem_c + OFF_BIAS + (0 * 32 + lane) * 4);
    const float biasF = *reinterpret_cast<float*>(smem_c + OFF_BIAS + (1 * 32 + lane) * 4);
    const float biasG = *reinterpret_cast<float*>(smem_c + OFF_BIAS + (2 * 32 + lane) * 4);
    const float biasO = *reinterpret_cast<float*>(smem_c + OFF_BIAS + (3 * 32 + lane) * 4);
    const float wout  = *reinterpret_cast<float*>(smem_c + OFF_WOUT + lane * 4);

    // this lane-pair's h-write WORD offset (even k of the pair): khe = 32 + j0 + (lane & ~1)
    const int khe = PP + j0 + (lane & ~1);
    const uint32_t hwrd4 = (uint32_t)((khe >> 4) * 8 + ((khe >> 1) & 3) * 2 + ((khe >> 3) & 1)) * 4;

    // smem base + peer bases
    uint32_t sbase;
    asm("{ .reg .u64 t0; cvta.to.shared.u64 t0, %1; cvt.u32.u64 %0, t0; }" : "=r"(sbase) : "l"(smem_c));
    uint32_t peer_base[CHUNK];
#pragma unroll
    for (int rr = 0; rr < CHUNK; ++rr)
        asm("mapa.shared::cluster.u32 %0, %1, %2;" : "=r"(peer_base[rr]) : "r"(sbase), "r"(rr));

    float c[4] = {0.0f, 0.0f, 0.0f, 0.0f};
    int buf = 0;

    // order init X staging before the loop's pre-wait local reads
    __syncthreads();

    // init done: release local init stores to the cluster (arrive #1)
    CLUSTER_ARRIVE();

    for (int t = 0; t < TT; ++t) {
        // prefetch X(t+1) from global BEFORE the wait — latency hidden by barrier+MMA
        int tn = (t + 1 < TT) ? (t + 1) : t;
        uint2 pvh = *reinterpret_cast<const uint2*>(&Xp_hi_g[((size_t)xb * TT + tn) * 16 + xwp]);
        uint2 pvl = *reinterpret_cast<const uint2*>(&Xp_lo_g[((size_t)xb * TT + tn) * 16 + xwp]);

        const char* bufhi = smem_c + OFF_B0 + buf * 2 * BBYTES;
        const char* buflo = bufhi + BBYTES;

        // 3 independent accumulator sets (one per split term) — chain depth 10 each
        float accA[4][4], accB[4][4], accC[4][4];
#pragma unroll
        for (int nt = 0; nt < 4; ++nt)
#pragma unroll
            for (int e = 0; e < 4; ++e) { accA[nt][e] = 0.0f; accB[nt][e] = 0.0f; accC[nt][e] = 0.0f; }

        // ---- x-part MMAs (k-tiles 0..1): X(t) is CTA-local — run BEFORE the wait ----
#pragma unroll
        for (int kt = 0; kt < 2; ++kt) {
            uint2 bh[4], bl[4];
#pragma unroll
            for (int nt = 0; nt < 4; ++nt) {
                uint32_t off = ((nt * 8 + r) * PADW + kt * 8 + tg * 2) * 4;
                bh[nt] = *reinterpret_cast<const uint2*>(bufhi + off);
                bl[nt] = *reinterpret_cast<const uint2*>(buflo + off);
            }
#pragma unroll
            for (int nt = 0; nt < 4; ++nt) mma16816(accA[nt], Ahi[kt], bh[nt].x, bh[nt].y);
#pragma unroll
            for (int nt = 0; nt < 4; ++nt) mma16816(accB[nt], Ahi[kt], bl[nt].x, bl[nt].y);
#pragma unroll
            for (int nt = 0; nt < 4; ++nt) mma16816(accC[nt], Alo[kt], bh[nt].x, bh[nt].y);
        }

        // wait: all CTAs published h(t) stores (arrive #(t+1))
        CLUSTER_WAIT();

        // ---- h-part MMAs (k-tiles 2..9) ----
#pragma unroll
        for (int kt = 2; kt < KTILES; ++kt) {
            uint2 bh[4], bl[4];
#pragma unroll
            for (int nt = 0; nt < 4; ++nt) {
                uint32_t off = ((nt * 8 + r) * PADW + kt * 8 + tg * 2) * 4;
                bh[nt] = *reinterpret_cast<const uint2*>(bufhi + off);
                bl[nt] = *reinterpret_cast<const uint2*>(buflo + off);
            }
#pragma unroll
            for (int nt = 0; nt < 4; ++nt) mma16816(accA[nt], Ahi[kt], bh[nt].x, bh[nt].y);
#pragma unroll
            for (int nt = 0; nt < 4; ++nt) mma16816(accB[nt], Ahi[kt], bl[nt].x, bl[nt].y);
#pragma unroll
            for (int nt = 0; nt < 4; ++nt) mma16816(accC[nt], Alo[kt], bh[nt].x, bh[nt].y);
        }

        // ---- stage D (= accA+accB+accC) -> S[g][jl][34 b] ----
        {
            const int g = wid >> 1;
            const int jlb = (wid & 1) * 16 + r;
#pragma unroll
            for (int nt = 0; nt < 4; ++nt) {
                int bcol = nt * 8 + tg * 2;
                float d0 = accA[nt][0] + accB[nt][0] + accC[nt][0];
                float d1 = accA[nt][1] + accB[nt][1] + accC[nt][1];
                float d2 = accA[nt][2] + accB[nt][2] + accC[nt][2];
                float d3 = accA[nt][3] + accB[nt][3] + accC[nt][3];
                *reinterpret_cast<float2*>(&S[(g * 32 + jlb) * S_PAD + bcol]) = make_float2(d0, d1);
                *reinterpret_cast<float2*>(&S[(g * 32 + jlb + 8) * S_PAD + bcol]) = make_float2(d2, d3);
            }
        }
        __syncthreads();

        const uint32_t offB_next = (uint32_t)(OFF_B0 + (buf ^ 1) * 2 * BBYTES);

        // ---- epilogue: activations + state + h broadcast ----
        float pout[4];
#pragma unroll
        for (int i = 0; i < 4; ++i) {
            int b = wid * 4 + i;
            float gi = S[(0 * 32 + lane) * S_PAD + b] + biasI;
            float gf = S[(1 * 32 + lane) * S_PAD + b] + biasF;
            float gg = S[(2 * 32 + lane) * S_PAD + b] + biasG;
            float go = S[(3 * 32 + lane) * S_PAD + b] + biasO;
            float ii = sigf(gi);
            float ff = sigf(gf);
            float g2 = tanha(gg);
            float oo = sigf(go);
            float cc = fmaf(ff, c[i], ii * g2);
            c[i] = cc;
            float h = oo * tanha(cc);

            __nv_bfloat16 hhb = __float2bfloat16(h);
            float rem = h - __bfloat162float(hhb);
            uint32_t vh = (uint32_t)__bfloat16_as_ushort(hhb);
            uint32_t vl = (uint32_t)__bfloat16_as_ushort(__float2bfloat16(rem));

            // pair up the two bf16 halves of each 32-bit B-word inside the warp
            uint32_t vhp = __shfl_down_sync(0xffffffffu, vh, 1);
            uint32_t vlp = __shfl_down_sync(0xffffffffu, vl, 1);
            if (!(lane & 1)) {
                uint32_t wordh = vh | (vhp << 16);
                uint32_t wordl = vl | (vlp << 16);
                uint32_t oh = offB_next + (uint32_t)b * (PADW * 4) + hwrd4;
                uint32_t ol = oh + BBYTES;
                // own CTA via plain shared store
                *reinterpret_cast<uint32_t*>(smem_c + oh) = wordh;
                *reinterpret_cast<uint32_t*>(smem_c + ol) = wordl;
                // peers via full-word cluster stores
#pragma unroll
                for (int rr = 0; rr < CHUNK; ++rr) {
                    if (rr != (int)rank) {
                        asm volatile("st.shared::cluster.u32 [%0], %1;" :: "r"(peer_base[rr] + oh), "r"(wordh) : "memory");
                        asm volatile("st.shared::cluster.u32 [%0], %1;" :: "r"(peer_base[rr] + ol), "r"(wordl) : "memory");
                    }
                }
            }
            pout[i] = h * wout;
        }

        // ---- stage X(t+1) from prefetch regs into next buffer ----
        *reinterpret_cast<uint2*>(smem_c + offB_next + (xb * PADW + xwp) * 4) = pvh;
        *reinterpret_cast<uint2*>(smem_c + offB_next + BBYTES + (xb * PADW + xwp) * 4) = pvl;

        // order X(t+1)/h local stores before next iteration's pre-wait reads
        __syncthreads();

        // release this step's stores to the cluster; head work hides under peer skew
        CLUSTER_ARRIVE();

        // head: reduce this CTA's 32 j's, accumulate to out (off critical path)
#pragma unroll
        for (int i = 0; i < 4; ++i) {
#pragma unroll
            for (int m = 16; m > 0; m >>= 1)
                pout[i] += __shfl_xor_sync(0xffffffffu, pout[i], m);
        }
        if (lane == 0) {
#pragma unroll
            for (int i = 0; i < 4; ++i)
                atomicAdd(&out[((size_t)(wid * 4 + i) * TT + t) * PP + n], pout[i]);
        }

        buf ^= 1;
    }

    // consume the final arrive; no CTA exits while peer stores may be in flight
    CLUSTER_WAIT();
}

extern "C" void kernel_launch(void* const* d_in, const int* in_sizes, int n_in,
                              void* d_out, int out_size) {
    const float* X    = (const float*)d_in[0];
    const float* Wih  = (const float*)d_in[1];
    const float* Whh  = (const float*)d_in[2];
    const float* bih  = (const float*)d_in[3];
    const float* bhh  = (const float*)d_in[4];
    const float* Wout = (const float*)d_in[5];
    const float* bout = (const float*)d_in[6];
    float* out = (float*)d_out;

    cudaFuncSetAttribute(clstm_mma_kernel, cudaFuncAttributeMaxDynamicSharedMemorySize, SMEM_BYTES);

    init_out_kernel<<<(BB * TT * PP + 255) / 256, 256>>>(out, bout);
    xsplit_kernel<<<(BB * TT * 16 + 255) / 256, 256>>>(X);
    clstm_mma_kernel<<<PP * CHUNK, NTHREADS, SMEM_BYTES>>>(Wih, Whh, bih, bhh, Wout, out);
}

// round 13
// speedup vs baseline: 1.9652x; 1.8815x over previous
#include <cuda_runtime.h>
#include <cuda_bf16.h>
#include <cstdint>

#define PP 32      // num networks
#define HH 128     // hidden
#define BB 32      // batch
#define TT 256     // seq len
#define NTHREADS 256
#define KTILES 10  // K = 160 = 10 x 16
#define NB 8       // batches per CTA

// B buffer: 8 batch-rows x PADW words (u32 = packed bf16 k-pair).
// PADW=90 -> row stride 360 B, conflict-free for fragment loads.
#define PADW 90
#define BHALF (NB * PADW * 4)            // 2880 (hi or lo block)
#define BBUF  (2 * BHALF)                // 5760 (hi+lo)

// smem byte offsets
#define OFF_BIAS 0                        // 4*128 f32 = 2048
#define OFF_WOUT 2048                     // 128 f32 = 512
#define OFF_B0   2560                     // 2 buffers x BBUF = 11520
#define OFF_ALO  14080                    // A_lo fragment table: 8w x 4mt x 10kt x 32 lanes x 16B
#define ALO_SIZE (8 * 4 * KTILES * 32 * 16)   // 163840
#define SMEM_BYTES (OFF_ALO + ALO_SIZE)   // 177920

// packed X scratch: [b][t][16 words] for k<32 region, hi and lo
__device__ uint32_t Xp_hi_g[BB * TT * 16];
__device__ uint32_t Xp_lo_g[BB * TT * 16];

__device__ __forceinline__ float tanha(float x) {
    float y; asm("tanh.approx.f32 %0, %1;" : "=f"(y) : "f"(x)); return y;
}
__device__ __forceinline__ float sigf(float x) {
    return fmaf(0.5f, tanha(0.5f * x), 0.5f);
}

__device__ __forceinline__ uint32_t pack_bf2(float lo_k, float hi_k) {
    unsigned short a = __bfloat16_as_ushort(__float2bfloat16(lo_k));
    unsigned short b = __bfloat16_as_ushort(__float2bfloat16(hi_k));
    return (uint32_t)a | ((uint32_t)b << 16);
}

__device__ __forceinline__ void mma16816(float* d, const uint32_t* a, uint32_t b0, uint32_t b1) {
    asm volatile(
        "mma.sync.aligned.m16n8k16.row.col.f32.bf16.bf16.f32 "
        "{%0,%1,%2,%3}, {%4,%5,%6,%7}, {%8,%9}, {%0,%1,%2,%3};"
        : "+f"(d[0]), "+f"(d[1]), "+f"(d[2]), "+f"(d[3])
        : "r"(a[0]), "r"(a[1]), "r"(a[2]), "r"(a[3]), "r"(b0), "r"(b1));
}

__global__ void init_out_kernel(float* __restrict__ out, const float* __restrict__ b_out) {
    int i = blockIdx.x * blockDim.x + threadIdx.x;
    if (i < BB * TT * PP) out[i] = b_out[i & (PP - 1)];
}

// split X into packed hi/lo bf16 word layout: word w of (b,t) holds k-pair at
// d0 = (w>>3)*16 + ((w&7)>>1)*2 + (w&1)*8
__global__ void xsplit_kernel(const float* __restrict__ X) {
    int i = blockIdx.x * blockDim.x + threadIdx.x;
    if (i >= BB * TT * 16) return;
    int w = i & 15;
    int bt = i >> 4;              // b*TT + t
    int d0 = ((w >> 3) * 16) + (((w & 7) >> 1) * 2) + ((w & 1) * 8);
    float v0 = X[(size_t)bt * PP + d0];
    float v1 = X[(size_t)bt * PP + d0 + 1];
    __nv_bfloat16 h0 = __float2bfloat16(v0);
    __nv_bfloat16 h1 = __float2bfloat16(v1);
    float l0 = v0 - __bfloat162float(h0);
    float l1 = v1 - __bfloat162float(h1);
    Xp_hi_g[i] = (uint32_t)__bfloat16_as_ushort(h0) | ((uint32_t)__bfloat16_as_ushort(h1) << 16);
    Xp_lo_g[i] = pack_bf2(l0, l1);
}

extern __shared__ char smem_c[];

__global__ void __launch_bounds__(NTHREADS, 1)
clstm_mma_kernel(const float* __restrict__ Wih,
                 const float* __restrict__ Whh,
                 const float* __restrict__ bih,
                 const float* __restrict__ bhh,
                 const float* __restrict__ Wout,
                 float* __restrict__ out)
{
    const int tid  = threadIdx.x;
    const int lane = tid & 31;
    const int wid  = tid >> 5;           // 8 warps; warp owns j in [wid*16, wid*16+16)
    const int r    = lane >> 2;          // fragment row group (0..7)
    const int tg   = lane & 3;           // fragment thread-in-group

    const int n  = blockIdx.x >> 2;      // network id
    const int bg = blockIdx.x & 3;       // batch group: global b = bg*8 + blocal
    const int j1 = wid * 16 + r;         // this thread's first j
    const int j2 = j1 + 8;               // second j

    // ---- zero both B buffers (h region must start at 0) ----
    {
        uint4 z = make_uint4(0, 0, 0, 0);
        for (int i = tid; i < 2 * BBUF / 16; i += NTHREADS)
            reinterpret_cast<uint4*>(smem_c + OFF_B0)[i] = z;
    }

    // ---- bias + wout for all 128 j ----
    for (int idx = tid; idx < 4 * HH; idx += NTHREADS) {
        int g = idx >> 7, j = idx & 127;
        int row = n * 4 * HH + g * HH + j;
        *reinterpret_cast<float*>(smem_c + OFF_BIAS + idx * 4) = bih[row] + bhh[row];
    }
    for (int idx = tid; idx < HH; idx += NTHREADS)
        *reinterpret_cast<float*>(smem_c + OFF_WOUT + idx * 4) = Wout[n * HH + idx];

    // ---- load A fragments: A_hi -> registers, A_lo -> smem fragment table ----
    // m-tile mt = gate mt; tile rows 0..7 -> j1, rows 8..15 -> j2.
    uint32_t Ahi[4][KTILES][4];
#pragma unroll
    for (int mt = 0; mt < 4; ++mt) {
        const size_t grow1 = (size_t)(n * 4 * HH + mt * HH + j1);
        const size_t grow2 = (size_t)(n * 4 * HH + mt * HH + j2);
#pragma unroll
        for (int kt = 0; kt < KTILES; ++kt) {
            uint32_t alo[4];
#pragma unroll
            for (int e = 0; e < 4; ++e) {
                // e: 0 -> (j1, k0), 1 -> (j2, k0), 2 -> (j1, k0+8), 3 -> (j2, k0+8)
                size_t grow = (e & 1) ? grow2 : grow1;
                int k = kt * 16 + tg * 2 + ((e >> 1) * 8);
                float v0, v1;
                if (k < PP) {
                    v0 = Wih[grow * PP + k];
                    v1 = Wih[grow * PP + k + 1];
                } else {
                    v0 = Whh[grow * HH + (k - PP)];
                    v1 = Whh[grow * HH + (k - PP) + 1];
                }
                __nv_bfloat16 h0 = __float2bfloat16(v0);
                __nv_bfloat16 h1 = __float2bfloat16(v1);
                Ahi[mt][kt][e] = (uint32_t)__bfloat16_as_ushort(h0) | ((uint32_t)__bfloat16_as_ushort(h1) << 16);
                alo[e] = pack_bf2(v0 - __bfloat162float(h0), v1 - __bfloat162float(h1));
            }
            // store A_lo fragment in exact reload layout: one LDS.128 per (mt,kt)
            uint32_t slot = OFF_ALO + (uint32_t)(((wid * 4 + mt) * KTILES + kt) * 32 + lane) * 16;
            *reinterpret_cast<uint4*>(smem_c + slot) = make_uint4(alo[0], alo[1], alo[2], alo[3]);
        }
    }

    // ordering: zero/bias/wout/A_lo writes before X staging & reads
    __syncthreads();

    // ---- stage X(t=0) into buffer 0 (threads 0..63) ----
    const int xbl = tid >> 3;            // batch local 0..7 (valid for tid<64)
    const int xwp = (tid & 7) * 2;
    const int xbg = bg * NB + xbl;       // global batch
    if (tid < 64) {
        uint2 vh = *reinterpret_cast<const uint2*>(&Xp_hi_g[((size_t)xbg * TT + 0) * 16 + xwp]);
        uint2 vl = *reinterpret_cast<const uint2*>(&Xp_lo_g[((size_t)xbg * TT + 0) * 16 + xwp]);
        *reinterpret_cast<uint2*>(smem_c + OFF_B0 + (xbl * PADW + xwp) * 4) = vh;
        *reinterpret_cast<uint2*>(smem_c + OFF_B0 + BHALF + (xbl * PADW + xwp) * 4) = vl;
    }

    // per-thread epilogue constants
    const float biasI1 = *reinterpret_cast<float*>(smem_c + OFF_BIAS + (0 * HH + j1) * 4);
    const float biasF1 = *reinterpret_cast<float*>(smem_c + OFF_BIAS + (1 * HH + j1) * 4);
    const float biasG1 = *reinterpret_cast<float*>(smem_c + OFF_BIAS + (2 * HH + j1) * 4);
    const float biasO1 = *reinterpret_cast<float*>(smem_c + OFF_BIAS + (3 * HH + j1) * 4);
    const float biasI2 = *reinterpret_cast<float*>(smem_c + OFF_BIAS + (0 * HH + j2) * 4);
    const float biasF2 = *reinterpret_cast<float*>(smem_c + OFF_BIAS + (1 * HH + j2) * 4);
    const float biasG2 = *reinterpret_cast<float*>(smem_c + OFF_BIAS + (2 * HH + j2) * 4);
    const float biasO2 = *reinterpret_cast<float*>(smem_c + OFF_BIAS + (3 * HH + j2) * 4);
    const float wout1  = *reinterpret_cast<float*>(smem_c + OFF_WOUT + j1 * 4);
    const float wout2  = *reinterpret_cast<float*>(smem_c + OFF_WOUT + j2 * 4);

    // h-write word offsets for j-pairs (even r packs (j, j+1)); k = 32 + j
    const int khe1 = PP + (j1 & ~1);
    const int khe2 = PP + (j2 & ~1);
    const uint32_t hw1 = (uint32_t)((khe1 >> 4) * 8 + ((khe1 >> 1) & 3) * 2 + ((khe1 >> 3) & 1)) * 4;
    const uint32_t hw2 = (uint32_t)((khe2 >> 4) * 8 + ((khe2 >> 1) & 3) * 2 + ((khe2 >> 3) & 1)) * 4;

    // cell state: idx = jj*2 + cc -> (j = jj?j2:j1, b = tg*2+cc)
    float c[4] = {0.0f, 0.0f, 0.0f, 0.0f};

    __syncthreads();

    const uint32_t alo_base = OFF_ALO + (uint32_t)(wid * 4 * KTILES * 32 + lane) * 16;

    for (int t = 0; t < TT; ++t) {
        const char* bufhi = smem_c + OFF_B0 + (t & 1) * BBUF;
        const char* buflo = bufhi + BHALF;
        const uint32_t offB_next = (uint32_t)(OFF_B0 + ((t & 1) ^ 1) * BBUF);

        // prefetch X(t+1)
        int tn = (t + 1 < TT) ? (t + 1) : t;
        uint2 pvh, pvl;
        if (tid < 64) {
            pvh = *reinterpret_cast<const uint2*>(&Xp_hi_g[((size_t)xbg * TT + tn) * 16 + xwp]);
            pvl = *reinterpret_cast<const uint2*>(&Xp_lo_g[((size_t)xbg * TT + tn) * 16 + xwp]);
        }

        // ---- split-GEMM: acc = A_hi*B_hi + A_hi*B_lo + A_lo*B_hi ----
        float acc[4][4];
#pragma unroll
        for (int mt = 0; mt < 4; ++mt)
#pragma unroll
            for (int e = 0; e < 4; ++e) acc[mt][e] = 0.0f;

#pragma unroll
        for (int kt = 0; kt < KTILES; ++kt) {
            uint32_t boff = (uint32_t)(r * PADW + kt * 8 + tg * 2) * 4;
            uint2 bh = *reinterpret_cast<const uint2*>(bufhi + boff);
            uint2 bl = *reinterpret_cast<const uint2*>(buflo + boff);
            uint4 al0 = *reinterpret_cast<const uint4*>(smem_c + alo_base + (uint32_t)(0 * KTILES + kt) * 512);
            uint4 al1 = *reinterpret_cast<const uint4*>(smem_c + alo_base + (uint32_t)(1 * KTILES + kt) * 512);
            uint4 al2 = *reinterpret_cast<const uint4*>(smem_c + alo_base + (uint32_t)(2 * KTILES + kt) * 512);
            uint4 al3 = *reinterpret_cast<const uint4*>(smem_c + alo_base + (uint32_t)(3 * KTILES + kt) * 512);
#pragma unroll
            for (int mt = 0; mt < 4; ++mt) mma16816(acc[mt], Ahi[mt][kt], bh.x, bh.y);
#pragma unroll
            for (int mt = 0; mt < 4; ++mt) mma16816(acc[mt], Ahi[mt][kt], bl.x, bl.y);
            {
                uint32_t a0[4] = {al0.x, al0.y, al0.z, al0.w};
                uint32_t a1[4] = {al1.x, al1.y, al1.z, al1.w};
                uint32_t a2[4] = {al2.x, al2.y, al2.z, al2.w};
                uint32_t a3[4] = {al3.x, al3.y, al3.z, al3.w};
                mma16816(acc[0], a0, bh.x, bh.y);
                mma16816(acc[1], a1, bh.x, bh.y);
                mma16816(acc[2], a2, bh.x, bh.y);
                mma16816(acc[3], a3, bh.x, bh.y);
            }
        }

        // ---- fused epilogue straight from accumulators ----
        float pb0 = 0.0f, pb1 = 0.0f;    // head partials for b = tg*2, tg*2+1
#pragma unroll
        for (int jj = 0; jj < 2; ++jj) {
            const float bI = jj ? biasI2 : biasI1;
            const float bF = jj ? biasF2 : biasF1;
            const float bG = jj ? biasG2 : biasG1;
            const float bO = jj ? biasO2 : biasO1;
            const float wo = jj ? wout2 : wout1;
            const uint32_t hw = jj ? hw2 : hw1;
            uint32_t wordh_acc[2], wordl_acc[2];
#pragma unroll
            for (int cc = 0; cc < 2; ++cc) {
                int idx = jj * 2 + cc;
                float gi = acc[0][idx] + bI;
                float gf = acc[1][idx] + bF;
                float gg = acc[2][idx] + bG;
                float go = acc[3][idx] + bO;
                float ii = sigf(gi);
                float ff = sigf(gf);
                float g2 = tanha(gg);
                float oo = sigf(go);
                float ncell = fmaf(ff, c[idx], ii * g2);
                c[idx] = ncell;
                float h = oo * tanha(ncell);

                __nv_bfloat16 hhb = __float2bfloat16(h);
                float rem = h - __bfloat162float(hhb);
                uint32_t vh = (uint32_t)__bfloat16_as_ushort(hhb);
                uint32_t vl = (uint32_t)__bfloat16_as_ushort(__float2bfloat16(rem));
                // pair j (even) with j+1 (lane r+1, i.e. lane+4)
                uint32_t vhp = __shfl_down_sync(0xffffffffu, vh, 4);
                uint32_t vlp = __shfl_down_sync(0xffffffffu, vl, 4);
                wordh_acc[cc] = vh | (vhp << 16);
                wordl_acc[cc] = vl | (vlp << 16);

                if (cc == 0) pb0 = fmaf(h, wo, pb0); else pb1 = fmaf(h, wo, pb1);
            }
            if (!(r & 1)) {
#pragma unroll
                for (int cc = 0; cc < 2; ++cc) {
                    uint32_t row = (uint32_t)(tg * 2 + cc) * (PADW * 4);
                    *reinterpret_cast<uint32_t*>(smem_c + offB_next + row + hw) = wordh_acc[cc];
                    *reinterpret_cast<uint32_t*>(smem_c + offB_next + BHALF + row + hw) = wordl_acc[cc];
                }
            }
        }

        // ---- stage X(t+1) into next buffer ----
        if (tid < 64) {
            *reinterpret_cast<uint2*>(smem_c + offB_next + (xbl * PADW + xwp) * 4) = pvh;
            *reinterpret_cast<uint2*>(smem_c + offB_next + BHALF + (xbl * PADW + xwp) * 4) = pvl;
        }

        // head: reduce over the warp's 16 j's (r axis: lane bits 2,3,4)
        pb0 += __shfl_xor_sync(0xffffffffu, pb0, 4);
        pb0 += __shfl_xor_sync(0xffffffffu, pb0, 8);
        pb0 += __shfl_xor_sync(0xffffffffu, pb0, 16);
        pb1 += __shfl_xor_sync(0xffffffffu, pb1, 4);
        pb1 += __shfl_xor_sync(0xffffffffu, pb1, 8);
        pb1 += __shfl_xor_sync(0xffffffffu, pb1, 16);
        if (r == 0) {
            int b0g = bg * NB + tg * 2;
            atomicAdd(&out[((size_t)b0g * TT + t) * PP + n], pb0);
            atomicAdd(&out[((size_t)(b0g + 1) * TT + t) * PP + n], pb1);
        }

        // order this step's h/X stores before next step's B loads
        __syncthreads();
    }
}

extern "C" void kernel_launch(void* const* d_in, const int* in_sizes, int n_in,
                              void* d_out, int out_size) {
    const float* X    = (const float*)d_in[0];
    const float* Wih  = (const float*)d_in[1];
    const float* Whh  = (const float*)d_in[2];
    const float* bih  = (const float*)d_in[3];
    const float* bhh  = (const float*)d_in[4];
    const float* Wout = (const float*)d_in[5];
    const float* bout = (const float*)d_in[6];
    float* out = (float*)d_out;

    cudaFuncSetAttribute(clstm_mma_kernel, cudaFuncAttributeMaxDynamicSharedMemorySize, SMEM_BYTES);

    init_out_kernel<<<(BB * TT * PP + 255) / 256, 256>>>(out, bout);
    xsplit_kernel<<<(BB * TT * 16 + 255) / 256, 256>>>(X);
    clstm_mma_kernel<<<PP * 4, NTHREADS, SMEM_BYTES>>>(Wih, Whh, bih, bhh, Wout, out);
}

// round 14
// speedup vs baseline: 2.3945x; 1.2184x over previous
#include <cuda_runtime.h>
#include <cuda_fp16.h>
#include <cstdint>

#define PP 32      // num networks
#define HH 128     // hidden
#define BB 32      // batch
#define TT 256     // seq len
#define NTHREADS 256
#define KTILES 10  // K = 160 = 10 x 16
#define NB 8       // batches per CTA

// B buffer: 8 batch-rows x PADW words (u32 = packed f16 k-pair), single precision level.
// PADW=90 -> row stride 360 B, conflict-free for fragment loads.
#define PADW 90
#define BBUF (NB * PADW * 4)             // 2880 per buffer

// smem byte offsets
#define OFF_BIAS 0                        // 4*128 f32 = 2048
#define OFF_WOUT 2048                     // 128 f32 = 512
#define OFF_B0   2560                     // 2 buffers x BBUF = 5760
#define OFF_ALO  8320                     // A_lo fragment table: 8w x 4mt x 10kt x 32 lanes x 16B
#define ALO_SIZE (8 * 4 * KTILES * 32 * 16)   // 163840
#define SMEM_BYTES (OFF_ALO + ALO_SIZE)   // 172160

// packed X scratch: [b][t][16 words], each word = f16 k-pair
__device__ uint32_t Xp_g[BB * TT * 16];

__device__ __forceinline__ float tanha(float x) {
    float y; asm("tanh.approx.f32 %0, %1;" : "=f"(y) : "f"(x)); return y;
}
__device__ __forceinline__ float sigf(float x) {
    return fmaf(0.5f, tanha(0.5f * x), 0.5f);
}

__device__ __forceinline__ uint32_t pack_h2(float lo_k, float hi_k) {
    __half a = __float2half_rn(lo_k);
    __half b = __float2half_rn(hi_k);
    return (uint32_t)__half_as_ushort(a) | ((uint32_t)__half_as_ushort(b) << 16);
}

__device__ __forceinline__ void mma16816(float* d, const uint32_t* a, uint32_t b0, uint32_t b1) {
    asm volatile(
        "mma.sync.aligned.m16n8k16.row.col.f32.f16.f16.f32 "
        "{%0,%1,%2,%3}, {%4,%5,%6,%7}, {%8,%9}, {%0,%1,%2,%3};"
        : "+f"(d[0]), "+f"(d[1]), "+f"(d[2]), "+f"(d[3])
        : "r"(a[0]), "r"(a[1]), "r"(a[2]), "r"(a[3]), "r"(b0), "r"(b1));
}

__global__ void init_out_kernel(float* __restrict__ out, const float* __restrict__ b_out) {
    int i = blockIdx.x * blockDim.x + threadIdx.x;
    if (i < BB * TT * PP) out[i] = b_out[i & (PP - 1)];
}

// pack X into f16 word layout: word w of (b,t) holds k-pair at
// d0 = (w>>3)*16 + ((w&7)>>1)*2 + (w&1)*8
__global__ void xsplit_kernel(const float* __restrict__ X) {
    int i = blockIdx.x * blockDim.x + threadIdx.x;
    if (i >= BB * TT * 16) return;
    int w = i & 15;
    int bt = i >> 4;              // b*TT + t
    int d0 = ((w >> 3) * 16) + (((w & 7) >> 1) * 2) + ((w & 1) * 8);
    float v0 = X[(size_t)bt * PP + d0];
    float v1 = X[(size_t)bt * PP + d0 + 1];
    Xp_g[i] = pack_h2(v0, v1);
}

extern __shared__ char smem_c[];

__global__ void __launch_bounds__(NTHREADS, 1)
clstm_mma_kernel(const float* __restrict__ Wih,
                 const float* __restrict__ Whh,
                 const float* __restrict__ bih,
                 const float* __restrict__ bhh,
                 const float* __restrict__ Wout,
                 float* __restrict__ out)
{
    const int tid  = threadIdx.x;
    const int lane = tid & 31;
    const int wid  = tid >> 5;           // 8 warps; warp owns j in [wid*16, wid*16+16)
    const int r    = lane >> 2;          // fragment row group (0..7)
    const int tg   = lane & 3;           // fragment thread-in-group

    const int n  = blockIdx.x >> 2;      // network id
    const int bg = blockIdx.x & 3;       // batch group: global b = bg*8 + blocal
    const int j1 = wid * 16 + r;         // this thread's first j
    const int j2 = j1 + 8;               // second j

    // ---- zero both B buffers (h region must start at 0) ----
    {
        uint4 z = make_uint4(0, 0, 0, 0);
        for (int i = tid; i < 2 * BBUF / 16; i += NTHREADS)
            reinterpret_cast<uint4*>(smem_c + OFF_B0)[i] = z;
    }

    // ---- bias + wout for all 128 j ----
    for (int idx = tid; idx < 4 * HH; idx += NTHREADS) {
        int g = idx >> 7, j = idx & 127;
        int row = n * 4 * HH + g * HH + j;
        *reinterpret_cast<float*>(smem_c + OFF_BIAS + idx * 4) = bih[row] + bhh[row];
    }
    for (int idx = tid; idx < HH; idx += NTHREADS)
        *reinterpret_cast<float*>(smem_c + OFF_WOUT + idx * 4) = Wout[n * HH + idx];

    // ---- load A fragments: A_hi (f16) -> registers, A_lo (f16 residual) -> smem table ----
    // m-tile mt = gate mt; tile rows 0..7 -> j1, rows 8..15 -> j2.
    uint32_t Ahi[4][KTILES][4];
#pragma unroll
    for (int mt = 0; mt < 4; ++mt) {
        const size_t grow1 = (size_t)(n * 4 * HH + mt * HH + j1);
        const size_t grow2 = (size_t)(n * 4 * HH + mt * HH + j2);
#pragma unroll
        for (int kt = 0; kt < KTILES; ++kt) {
            uint32_t alo[4];
#pragma unroll
            for (int e = 0; e < 4; ++e) {
                // e: 0 -> (j1, k0), 1 -> (j2, k0), 2 -> (j1, k0+8), 3 -> (j2, k0+8)
                size_t grow = (e & 1) ? grow2 : grow1;
                int k = kt * 16 + tg * 2 + ((e >> 1) * 8);
                float v0, v1;
                if (k < PP) {
                    v0 = Wih[grow * PP + k];
                    v1 = Wih[grow * PP + k + 1];
                } else {
                    v0 = Whh[grow * HH + (k - PP)];
                    v1 = Whh[grow * HH + (k - PP) + 1];
                }
                __half h0 = __float2half_rn(v0);
                __half h1 = __float2half_rn(v1);
                Ahi[mt][kt][e] = (uint32_t)__half_as_ushort(h0) | ((uint32_t)__half_as_ushort(h1) << 16);
                alo[e] = pack_h2(v0 - __half2float(h0), v1 - __half2float(h1));
            }
            // store A_lo fragment in exact reload layout: one LDS.128 per (mt,kt)
            uint32_t slot = OFF_ALO + (uint32_t)(((wid * 4 + mt) * KTILES + kt) * 32 + lane) * 16;
            *reinterpret_cast<uint4*>(smem_c + slot) = make_uint4(alo[0], alo[1], alo[2], alo[3]);
        }
    }

    // ordering: zero/bias/wout/A_lo writes before X staging & reads
    __syncthreads();

    // ---- stage X(t=0) into buffer 0 (threads 0..63) ----
    const int xbl = tid >> 3;            // batch local 0..7 (valid for tid<64)
    const int xwp = (tid & 7) * 2;
    const int xbg = bg * NB + xbl;       // global batch
    if (tid < 64) {
        uint2 v = *reinterpret_cast<const uint2*>(&Xp_g[((size_t)xbg * TT + 0) * 16 + xwp]);
        *reinterpret_cast<uint2*>(smem_c + OFF_B0 + (xbl * PADW + xwp) * 4) = v;
    }

    // per-thread epilogue constants
    const float biasI1 = *reinterpret_cast<float*>(smem_c + OFF_BIAS + (0 * HH + j1) * 4);
    const float biasF1 = *reinterpret_cast<float*>(smem_c + OFF_BIAS + (1 * HH + j1) * 4);
    const float biasG1 = *reinterpret_cast<float*>(smem_c + OFF_BIAS + (2 * HH + j1) * 4);
    const float biasO1 = *reinterpret_cast<float*>(smem_c + OFF_BIAS + (3 * HH + j1) * 4);
    const float biasI2 = *reinterpret_cast<float*>(smem_c + OFF_BIAS + (0 * HH + j2) * 4);
    const float biasF2 = *reinterpret_cast<float*>(smem_c + OFF_BIAS + (1 * HH + j2) * 4);
    const float biasG2 = *reinterpret_cast<float*>(smem_c + OFF_BIAS + (2 * HH + j2) * 4);
    const float biasO2 = *reinterpret_cast<float*>(smem_c + OFF_BIAS + (3 * HH + j2) * 4);
    const float wout1  = *reinterpret_cast<float*>(smem_c + OFF_WOUT + j1 * 4);
    const float wout2  = *reinterpret_cast<float*>(smem_c + OFF_WOUT + j2 * 4);

    // h-write word offsets for j-pairs (even r packs (j, j+1)); k = 32 + j
    const int khe1 = PP + (j1 & ~1);
    const int khe2 = PP + (j2 & ~1);
    const uint32_t hw1 = (uint32_t)((khe1 >> 4) * 8 + ((khe1 >> 1) & 3) * 2 + ((khe1 >> 3) & 1)) * 4;
    const uint32_t hw2 = (uint32_t)((khe2 >> 4) * 8 + ((khe2 >> 1) & 3) * 2 + ((khe2 >> 3) & 1)) * 4;

    // cell state: idx = jj*2 + cc -> (j = jj?j2:j1, b = tg*2+cc)
    float c[4] = {0.0f, 0.0f, 0.0f, 0.0f};

    __syncthreads();

    const uint32_t alo_base = OFF_ALO + (uint32_t)(wid * 4 * KTILES * 32 + lane) * 16;

    for (int t = 0; t < TT; ++t) {
        const char* bufp = smem_c + OFF_B0 + (t & 1) * BBUF;
        const uint32_t offB_next = (uint32_t)(OFF_B0 + ((t & 1) ^ 1) * BBUF);

        // prefetch X(t+1)
        int tn = (t + 1 < TT) ? (t + 1) : t;
        uint2 pv;
        if (tid < 64)
            pv = *reinterpret_cast<const uint2*>(&Xp_g[((size_t)xbg * TT + tn) * 16 + xwp]);

        // ---- 2-term split-GEMM: acc = A_hi*B + A_lo*B  (W = Ahi+Alo exact-ish, B f16) ----
        float acc[4][4];
#pragma unroll
        for (int mt = 0; mt < 4; ++mt)
#pragma unroll
            for (int e = 0; e < 4; ++e) acc[mt][e] = 0.0f;

#pragma unroll
        for (int kt = 0; kt < KTILES; ++kt) {
            uint32_t boff = (uint32_t)(r * PADW + kt * 8 + tg * 2) * 4;
            uint2 bh = *reinterpret_cast<const uint2*>(bufp + boff);
            uint4 al0 = *reinterpret_cast<const uint4*>(smem_c + alo_base + (uint32_t)(0 * KTILES + kt) * 512);
            uint4 al1 = *reinterpret_cast<const uint4*>(smem_c + alo_base + (uint32_t)(1 * KTILES + kt) * 512);
            uint4 al2 = *reinterpret_cast<const uint4*>(smem_c + alo_base + (uint32_t)(2 * KTILES + kt) * 512);
            uint4 al3 = *reinterpret_cast<const uint4*>(smem_c + alo_base + (uint32_t)(3 * KTILES + kt) * 512);
#pragma unroll
            for (int mt = 0; mt < 4; ++mt) mma16816(acc[mt], Ahi[mt][kt], bh.x, bh.y);
            {
                uint32_t a0[4] = {al0.x, al0.y, al0.z, al0.w};
                uint32_t a1[4] = {al1.x, al1.y, al1.z, al1.w};
                uint32_t a2[4] = {al2.x, al2.y, al2.z, al2.w};
                uint32_t a3[4] = {al3.x, al3.y, al3.z, al3.w};
                mma16816(acc[0], a0, bh.x, bh.y);
                mma16816(acc[1], a1, bh.x, bh.y);
                mma16816(acc[2], a2, bh.x, bh.y);
                mma16816(acc[3], a3, bh.x, bh.y);
            }
        }

        // ---- fused epilogue straight from accumulators ----
        float pb0 = 0.0f, pb1 = 0.0f;    // head partials for b = tg*2, tg*2+1
#pragma unroll
        for (int jj = 0; jj < 2; ++jj) {
            const float bI = jj ? biasI2 : biasI1;
            const float bF = jj ? biasF2 : biasF1;
            const float bG = jj ? biasG2 : biasG1;
            const float bO = jj ? biasO2 : biasO1;
            const float wo = jj ? wout2 : wout1;
            const uint32_t hw = jj ? hw2 : hw1;
            uint32_t word_acc[2];
#pragma unroll
            for (int cc = 0; cc < 2; ++cc) {
                int idx = jj * 2 + cc;
                float gi = acc[0][idx] + bI;
                float gf = acc[1][idx] + bF;
                float gg = acc[2][idx] + bG;
                float go = acc[3][idx] + bO;
                float ii = sigf(gi);
                float ff = sigf(gf);
                float g2 = tanha(gg);
                float oo = sigf(go);
                float ncell = fmaf(ff, c[idx], ii * g2);
                c[idx] = ncell;
                float h = oo * tanha(ncell);

                uint32_t vh = (uint32_t)__half_as_ushort(__float2half_rn(h));
                // pair j (even) with j+1 (lane r+1, i.e. lane+4)
                uint32_t vhp = __shfl_down_sync(0xffffffffu, vh, 4);
                word_acc[cc] = vh | (vhp << 16);

                if (cc == 0) pb0 = fmaf(h, wo, pb0); else pb1 = fmaf(h, wo, pb1);
            }
            if (!(r & 1)) {
#pragma unroll
                for (int cc = 0; cc < 2; ++cc) {
                    uint32_t row = (uint32_t)(tg * 2 + cc) * (PADW * 4);
                    *reinterpret_cast<uint32_t*>(smem_c + offB_next + row + hw) = word_acc[cc];
                }
            }
        }

        // ---- stage X(t+1) into next buffer ----
        if (tid < 64)
            *reinterpret_cast<uint2*>(smem_c + offB_next + (xbl * PADW + xwp) * 4) = pv;

        // head: reduce over the warp's 16 j's (r axis: lane bits 2,3,4)
        pb0 += __shfl_xor_sync(0xffffffffu, pb0, 4);
        pb0 += __shfl_xor_sync(0xffffffffu, pb0, 8);
        pb0 += __shfl_xor_sync(0xffffffffu, pb0, 16);
        pb1 += __shfl_xor_sync(0xffffffffu, pb1, 4);
        pb1 += __shfl_xor_sync(0xffffffffu, pb1, 8);
        pb1 += __shfl_xor_sync(0xffffffffu, pb1, 16);
        if (r == 0) {
            int b0g = bg * NB + tg * 2;
            atomicAdd(&out[((size_t)b0g * TT + t) * PP + n], pb0);
            atomicAdd(&out[((size_t)(b0g + 1) * TT + t) * PP + n], pb1);
        }

        // order this step's h/X stores before next step's B loads
        __syncthreads();
    }
}

extern "C" void kernel_launch(void* const* d_in, const int* in_sizes, int n_in,
                              void* d_out, int out_size) {
    const float* X    = (const float*)d_in[0];
    const float* Wih  = (const float*)d_in[1];
    const float* Whh  = (const float*)d_in[2];
    const float* bih  = (const float*)d_in[3];
    const float* bhh  = (const float*)d_in[4];
    const float* Wout = (const float*)d_in[5];
    const float* bout = (const float*)d_in[6];
    float* out = (float*)d_out;

    cudaFuncSetAttribute(clstm_mma_kernel, cudaFuncAttributeMaxDynamicSharedMemorySize, SMEM_BYTES);

    init_out_kernel<<<(BB * TT * PP + 255) / 256, 256>>>(out, bout);
    xsplit_kernel<<<(BB * TT * 16 + 255) / 256, 256>>>(X);
    clstm_mma_kernel<<<PP * 4, NTHREADS, SMEM_BYTES>>>(Wih, Whh, bih, bhh, Wout, out);
}

// round 15
// speedup vs baseline: 4.3078x; 1.7990x over previous
#include <cuda_runtime.h>
#include <cuda_fp16.h>
#include <cstdint>

#define PP 32      // num networks
#define HH 128     // hidden
#define BB 32      // batch
#define TT 256     // seq len
#define NTHREADS 256
#define KTILES 10  // K = 160 = 10 x 16
#define NB 8       // batches per CTA

// B buffer: 8 batch-rows x PADW words (u32 = packed f16 k-pair).
// PADW=90 -> row stride 360 B, conflict-free for fragment loads.
#define PADW 90
#define BBUF (NB * PADW * 4)             // 2880 per buffer

// smem byte offsets
#define OFF_BIAS 0                        // 4*128 f32 = 2048
#define OFF_WOUT 2048                     // 128 f32 = 512
#define OFF_B0   2560                     // 2 buffers x BBUF = 5760
#define SMEM_BYTES (OFF_B0 + 2 * BBUF)    // 8320

// packed X scratch: [b][t][16 words], each word = f16 k-pair
__device__ uint32_t Xp_g[BB * TT * 16];

__device__ __forceinline__ float tanha(float x) {
    float y; asm("tanh.approx.f32 %0, %1;" : "=f"(y) : "f"(x)); return y;
}
__device__ __forceinline__ float sigf(float x) {
    return fmaf(0.5f, tanha(0.5f * x), 0.5f);
}

__device__ __forceinline__ uint32_t pack_h2(float lo_k, float hi_k) {
    __half a = __float2half_rn(lo_k);
    __half b = __float2half_rn(hi_k);
    return (uint32_t)__half_as_ushort(a) | ((uint32_t)__half_as_ushort(b) << 16);
}

__device__ __forceinline__ void mma16816(float* d, const uint32_t* a, uint32_t b0, uint32_t b1) {
    asm volatile(
        "mma.sync.aligned.m16n8k16.row.col.f32.f16.f16.f32 "
        "{%0,%1,%2,%3}, {%4,%5,%6,%7}, {%8,%9}, {%0,%1,%2,%3};"
        : "+f"(d[0]), "+f"(d[1]), "+f"(d[2]), "+f"(d[3])
        : "r"(a[0]), "r"(a[1]), "r"(a[2]), "r"(a[3]), "r"(b0), "r"(b1));
}

__global__ void init_out_kernel(float* __restrict__ out, const float* __restrict__ b_out) {
    int i = blockIdx.x * blockDim.x + threadIdx.x;
    if (i < BB * TT * PP) out[i] = b_out[i & (PP - 1)];
}

// pack X into f16 word layout: word w of (b,t) holds k-pair at
// d0 = (w>>3)*16 + ((w&7)>>1)*2 + (w&1)*8
__global__ void xsplit_kernel(const float* __restrict__ X) {
    int i = blockIdx.x * blockDim.x + threadIdx.x;
    if (i >= BB * TT * 16) return;
    int w = i & 15;
    int bt = i >> 4;              // b*TT + t
    int d0 = ((w >> 3) * 16) + (((w & 7) >> 1) * 2) + ((w & 1) * 8);
    float v0 = X[(size_t)bt * PP + d0];
    float v1 = X[(size_t)bt * PP + d0 + 1];
    Xp_g[i] = pack_h2(v0, v1);
}

extern __shared__ char smem_c[];

__global__ void __launch_bounds__(NTHREADS, 1)
clstm_mma_kernel(const float* __restrict__ Wih,
                 const float* __restrict__ Whh,
                 const float* __restrict__ bih,
                 const float* __restrict__ bhh,
                 const float* __restrict__ Wout,
                 float* __restrict__ out)
{
    const int tid  = threadIdx.x;
    const int lane = tid & 31;
    const int wid  = tid >> 5;           // 8 warps; warp owns j in [wid*16, wid*16+16)
    const int r    = lane >> 2;          // fragment row group (0..7)
    const int tg   = lane & 3;           // fragment thread-in-group

    const int n  = blockIdx.x >> 2;      // network id
    const int bg = blockIdx.x & 3;       // batch group: global b = bg*8 + blocal
    const int j1 = wid * 16 + r;         // this thread's first j
    const int j2 = j1 + 8;               // second j

    // ---- zero both B buffers (h region must start at 0) ----
    {
        uint4 z = make_uint4(0, 0, 0, 0);
        for (int i = tid; i < 2 * BBUF / 16; i += NTHREADS)
            reinterpret_cast<uint4*>(smem_c + OFF_B0)[i] = z;
    }

    // ---- bias + wout for all 128 j ----
    for (int idx = tid; idx < 4 * HH; idx += NTHREADS) {
        int g = idx >> 7, j = idx & 127;
        int row = n * 4 * HH + g * HH + j;
        *reinterpret_cast<float*>(smem_c + OFF_BIAS + idx * 4) = bih[row] + bhh[row];
    }
    for (int idx = tid; idx < HH; idx += NTHREADS)
        *reinterpret_cast<float*>(smem_c + OFF_WOUT + idx * 4) = Wout[n * HH + idx];

    // ---- load A fragments (f16) into registers ----
    // m-tile mt = gate mt; tile rows 0..7 -> j1, rows 8..15 -> j2.
    uint32_t Ah[4][KTILES][4];
#pragma unroll
    for (int mt = 0; mt < 4; ++mt) {
        const size_t grow1 = (size_t)(n * 4 * HH + mt * HH + j1);
        const size_t grow2 = (size_t)(n * 4 * HH + mt * HH + j2);
#pragma unroll
        for (int kt = 0; kt < KTILES; ++kt) {
#pragma unroll
            for (int e = 0; e < 4; ++e) {
                // e: 0 -> (j1, k0), 1 -> (j2, k0), 2 -> (j1, k0+8), 3 -> (j2, k0+8)
                size_t grow = (e & 1) ? grow2 : grow1;
                int k = kt * 16 + tg * 2 + ((e >> 1) * 8);
                float v0, v1;
                if (k < PP) {
                    v0 = Wih[grow * PP + k];
                    v1 = Wih[grow * PP + k + 1];
                } else {
                    v0 = Whh[grow * HH + (k - PP)];
                    v1 = Whh[grow * HH + (k - PP) + 1];
                }
                Ah[mt][kt][e] = pack_h2(v0, v1);
            }
        }
    }

    // ordering: zero/bias/wout writes before X staging & reads
    __syncthreads();

    // ---- stage X(t=0) into buffer 0 (threads 0..63) ----
    const int xbl = tid >> 3;            // batch local 0..7 (valid for tid<64)
    const int xwp = (tid & 7) * 2;
    const int xbg = bg * NB + xbl;       // global batch
    if (tid < 64) {
        uint2 v = *reinterpret_cast<const uint2*>(&Xp_g[((size_t)xbg * TT + 0) * 16 + xwp]);
        *reinterpret_cast<uint2*>(smem_c + OFF_B0 + (xbl * PADW + xwp) * 4) = v;
    }

    // per-thread epilogue constants
    const float biasI1 = *reinterpret_cast<float*>(smem_c + OFF_BIAS + (0 * HH + j1) * 4);
    const float biasF1 = *reinterpret_cast<float*>(smem_c + OFF_BIAS + (1 * HH + j1) * 4);
    const float biasG1 = *reinterpret_cast<float*>(smem_c + OFF_BIAS + (2 * HH + j1) * 4);
    const float biasO1 = *reinterpret_cast<float*>(smem_c + OFF_BIAS + (3 * HH + j1) * 4);
    const float biasI2 = *reinterpret_cast<float*>(smem_c + OFF_BIAS + (0 * HH + j2) * 4);
    const float biasF2 = *reinterpret_cast<float*>(smem_c + OFF_BIAS + (1 * HH + j2) * 4);
    const float biasG2 = *reinterpret_cast<float*>(smem_c + OFF_BIAS + (2 * HH + j2) * 4);
    const float biasO2 = *reinterpret_cast<float*>(smem_c + OFF_BIAS + (3 * HH + j2) * 4);
    const float wout1  = *reinterpret_cast<float*>(smem_c + OFF_WOUT + j1 * 4);
    const float wout2  = *reinterpret_cast<float*>(smem_c + OFF_WOUT + j2 * 4);

    // h-write word offsets for j-pairs (even r packs (j, j+1)); k = 32 + j
    const int khe1 = PP + (j1 & ~1);
    const int khe2 = PP + (j2 & ~1);
    const uint32_t hw1 = (uint32_t)((khe1 >> 4) * 8 + ((khe1 >> 1) & 3) * 2 + ((khe1 >> 3) & 1)) * 4;
    const uint32_t hw2 = (uint32_t)((khe2 >> 4) * 8 + ((khe2 >> 1) & 3) * 2 + ((khe2 >> 3) & 1)) * 4;

    // cell state: idx = jj*2 + cc -> (j = jj?j2:j1, b = tg*2+cc)
    float c[4] = {0.0f, 0.0f, 0.0f, 0.0f};

    __syncthreads();

    for (int t = 0; t < TT; ++t) {
        const char* bufp = smem_c + OFF_B0 + (t & 1) * BBUF;
        const uint32_t offB_next = (uint32_t)(OFF_B0 + ((t & 1) ^ 1) * BBUF);

        // prefetch X(t+1)
        int tn = (t + 1 < TT) ? (t + 1) : t;
        uint2 pv;
        if (tid < 64)
            pv = *reinterpret_cast<const uint2*>(&Xp_g[((size_t)xbg * TT + tn) * 16 + xwp]);

        // ---- plain f16 GEMM: 4 m-tiles x 10 k-tiles ----
        float acc[4][4];
#pragma unroll
        for (int mt = 0; mt < 4; ++mt)
#pragma unroll
            for (int e = 0; e < 4; ++e) acc[mt][e] = 0.0f;

#pragma unroll
        for (int kt = 0; kt < KTILES; ++kt) {
            uint32_t boff = (uint32_t)(r * PADW + kt * 8 + tg * 2) * 4;
            uint2 bh = *reinterpret_cast<const uint2*>(bufp + boff);
#pragma unroll
            for (int mt = 0; mt < 4; ++mt) mma16816(acc[mt], Ah[mt][kt], bh.x, bh.y);
        }

        // ---- fused epilogue straight from accumulators ----
        float pb0 = 0.0f, pb1 = 0.0f;    // head partials for b = tg*2, tg*2+1
#pragma unroll
        for (int jj = 0; jj < 2; ++jj) {
            const float bI = jj ? biasI2 : biasI1;
            const float bF = jj ? biasF2 : biasF1;
            const float bG = jj ? biasG2 : biasG1;
            const float bO = jj ? biasO2 : biasO1;
            const float wo = jj ? wout2 : wout1;
            const uint32_t hw = jj ? hw2 : hw1;
            uint32_t word_acc[2];
#pragma unroll
            for (int cc = 0; cc < 2; ++cc) {
                int idx = jj * 2 + cc;
                float gi = acc[0][idx] + bI;
                float gf = acc[1][idx] + bF;
                float gg = acc[2][idx] + bG;
                float go = acc[3][idx] + bO;
                float ii = sigf(gi);
                float ff = sigf(gf);
                float g2 = tanha(gg);
                float oo = sigf(go);
                float ncell = fmaf(ff, c[idx], ii * g2);
                c[idx] = ncell;
                float h = oo * tanha(ncell);

                uint32_t vh = (uint32_t)__half_as_ushort(__float2half_rn(h));
                // pair j (even) with j+1 (lane r+1, i.e. lane+4)
                uint32_t vhp = __shfl_down_sync(0xffffffffu, vh, 4);
                word_acc[cc] = vh | (vhp << 16);

                if (cc == 0) pb0 = fmaf(h, wo, pb0); else pb1 = fmaf(h, wo, pb1);
            }
            if (!(r & 1)) {
#pragma unroll
                for (int cc = 0; cc < 2; ++cc) {
                    uint32_t row = (uint32_t)(tg * 2 + cc) * (PADW * 4);
                    *reinterpret_cast<uint32_t*>(smem_c + offB_next + row + hw) = word_acc[cc];
                }
            }
        }

        // ---- stage X(t+1) into next buffer ----
        if (tid < 64)
            *reinterpret_cast<uint2*>(smem_c + offB_next + (xbl * PADW + xwp) * 4) = pv;

        // head: reduce over the warp's 16 j's (r axis: lane bits 2,3,4)
        pb0 += __shfl_xor_sync(0xffffffffu, pb0, 4);
        pb0 += __shfl_xor_sync(0xffffffffu, pb0, 8);
        pb0 += __shfl_xor_sync(0xffffffffu, pb0, 16);
        pb1 += __shfl_xor_sync(0xffffffffu, pb1, 4);
        pb1 += __shfl_xor_sync(0xffffffffu, pb1, 8);
        pb1 += __shfl_xor_sync(0xffffffffu, pb1, 16);
        if (r == 0) {
            int b0g = bg * NB + tg * 2;
            atomicAdd(&out[((size_t)b0g * TT + t) * PP + n], pb0);
            atomicAdd(&out[((size_t)(b0g + 1) * TT + t) * PP + n], pb1);
        }

        // order this step's h/X stores before next step's B loads
        __syncthreads();
    }
}

extern "C" void kernel_launch(void* const* d_in, const int* in_sizes, int n_in,
                              void* d_out, int out_size) {
    const float* X    = (const float*)d_in[0];
    const float* Wih  = (const float*)d_in[1];
    const float* Whh  = (const float*)d_in[2];
    const float* bih  = (const float*)d_in[3];
    const float* bhh  = (const float*)d_in[4];
    const float* Wout = (const float*)d_in[5];
    const float* bout = (const float*)d_in[6];
    float* out = (float*)d_out;

    cudaFuncSetAttribute(clstm_mma_kernel, cudaFuncAttributeMaxDynamicSharedMemorySize, SMEM_BYTES);

    init_out_kernel<<<(BB * TT * PP + 255) / 256, 256>>>(out, bout);
    xsplit_kernel<<<(BB * TT * 16 + 255) / 256, 256>>>(X);
    clstm_mma_kernel<<<PP * 4, NTHREADS, SMEM_BYTES>>>(Wih, Whh, bih, bhh, Wout, out);
}